// round 11
// baseline (speedup 1.0000x reference)
#include <cuda_runtime.h>
#include <cuda_bf16.h>
#include <cstdint>

// Per edge: out[o][t] = sum_k W[o][k] * x[k][t] + b[o],  O=K=64, T=256, E=10000
// mma.sync m16n8k16 bf16, 3-term split: D = wh*xh + wh*xl + wl*xh (rel ~2^-18).
// R11: one CTA per HALF-edge; D = W·x with m=o, n=t so fragments store DIRECTLY
//      to gmem (32B sector-aligned float2 per lane-quad) — no smem transpose.
//   A = W[o][k] (ldmatrix non-trans, regs reordered), B = x[k][t] (ldmatrix.trans).

#define T_DIM 256
#define K_DIM 64
#define O_DIM 64

// smem pitches (16B-chunk strides odd => conflict-free ldmatrix):
//   x: 136 bf16 = 272B = 17 chunks;  W: 72 bf16 = 144B = 9 chunks
#define WH_OFF   0u        // 64*144 = 9216
#define WL_OFF   9216u
#define BIAS_OFF 18432u    // 256B, pad to 18944
#define XH_OFF   18944u    // 64*272 = 17408 -> 36352
#define XL_OFF   36352u    // -> 53760
#define SMEM_BYTES 53760

static __device__ __forceinline__ uint32_t s2u(const void* p) {
    uint32_t a;
    asm("{ .reg .u64 t; cvta.to.shared.u64 t, %1; cvt.u32.u64 %0, t; }" : "=r"(a) : "l"(p));
    return a;
}

// split (a,b) into packed bf16x2 hi and lo pairs (a -> low half, memory order)
static __device__ __forceinline__ void split2(float a, float b, uint32_t& hp, uint32_t& lp) {
    __nv_bfloat16 ha = __float2bfloat16(a), hb = __float2bfloat16(b);
    float ra = a - __bfloat162float(ha);
    float rb = b - __bfloat162float(hb);
    __nv_bfloat16 la = __float2bfloat16(ra), lb = __float2bfloat16(rb);
    hp = (uint32_t)__bfloat16_as_ushort(ha) | ((uint32_t)__bfloat16_as_ushort(hb) << 16);
    lp = (uint32_t)__bfloat16_as_ushort(la) | ((uint32_t)__bfloat16_as_ushort(lb) << 16);
}

#define LDSM4(r, addr) \
    asm volatile("ldmatrix.sync.aligned.m8n8.x4.shared.b16 {%0,%1,%2,%3}, [%4];" \
        : "=r"((r)[0]), "=r"((r)[1]), "=r"((r)[2]), "=r"((r)[3]) : "r"(addr))

#define LDSM4T(r, addr) \
    asm volatile("ldmatrix.sync.aligned.m8n8.x4.trans.shared.b16 {%0,%1,%2,%3}, [%4];" \
        : "=r"((r)[0]), "=r"((r)[1]), "=r"((r)[2]), "=r"((r)[3]) : "r"(addr))

// A regs given explicitly (reordered from LDSM4), B = two regs
#define MMA_R(c, a0, a1, a2, a3, b0, b1) \
    asm volatile("mma.sync.aligned.m16n8k16.row.col.f32.bf16.bf16.f32 " \
        "{%0,%1,%2,%3}, {%4,%5,%6,%7}, {%8,%9}, {%0,%1,%2,%3};" \
        : "+f"((c)[0]), "+f"((c)[1]), "+f"((c)[2]), "+f"((c)[3]) \
        : "r"(a0), "r"(a1), "r"(a2), "r"(a3), "r"(b0), "r"(b1))

__global__ void __launch_bounds__(256, 4)
pl_hmma_direct_kernel(const float* __restrict__ x, const float* __restrict__ W,
                      const float* __restrict__ b, float* __restrict__ out)
{
    extern __shared__ char base[];
    const uint32_t sb = s2u(base);

    const int tid = threadIdx.x, wid = tid >> 5, lane = tid & 31;
    const int e  = blockIdx.x >> 1;          // edge
    const int th = blockIdx.x & 1;           // t-half: siblings adjacent -> W L2-hits
    const float* xg = x + (size_t)e * (K_DIM * T_DIM) + th * 128;
    const float* wg = W + (size_t)e * (O_DIM * K_DIM);
    const float* bg = b + (size_t)e * O_DIM;
    float*       og = out + (size_t)e * (O_DIM * T_DIM) + th * 128;

    // ---- Stage W -> (wh, wl) bf16, pitch 144B ----
    {
        const float4* wg4 = (const float4*)wg;
        #pragma unroll
        for (int i = 0; i < 4; i++) {
            const int f  = tid + (i << 8);         // 0..1023
            const int o  = f >> 4;
            const int kc = f & 15;                 // float4 within row
            float4 v = wg4[f];
            uint2 h, l;
            split2(v.x, v.y, h.x, l.x);
            split2(v.z, v.w, h.y, l.y);
            const uint32_t off = (uint32_t)o * 144u + (uint32_t)kc * 8u;
            *(uint2*)(base + WH_OFF + off) = h;
            *(uint2*)(base + WL_OFF + off) = l;
        }
    }
    // ---- Stage x half -> (xh, xl) bf16, pitch 272B (128 t per row) ----
    {
        #pragma unroll
        for (int i = 0; i < 8; i++) {
            const int f  = tid + (i << 8);         // 0..2047 float4s
            const int k  = f >> 5;                 // 32 float4 per local row
            const int c4 = f & 31;
            float4 v = *(const float4*)(xg + (size_t)k * T_DIM + (c4 << 2));
            uint2 h, l;
            split2(v.x, v.y, h.x, l.x);
            split2(v.z, v.w, h.y, l.y);
            const uint32_t off = (uint32_t)k * 272u + (uint32_t)c4 * 8u;
            *(uint2*)(base + XH_OFF + off) = h;
            *(uint2*)(base + XL_OFF + off) = l;
        }
    }
    if (tid < 64) *(float*)(base + BIAS_OFF + tid * 4) = bg[tid];
    __syncthreads();

    // ---- Per-warp tile: o in [0,64), t_loc in [16*wid, 16*wid+16) ----
    const int t_loc = wid << 4;
    const int lrow  = lane >> 2;       // fragment row (o within tile) / B n index
    const int lcol2 = (lane & 3) << 1; // fragment col pair base (t within n-tile)
    const int lm = lane >> 3, lr = lane & 7;

    // c[mo][nt][4]: rows o = mo*16 + lrow (+8 for regs 2,3), cols t = nt*8 + lcol2
    float c[4][2][4];
    {
        const float* bs = (const float*)(base + BIAS_OFF);
        #pragma unroll
        for (int mo = 0; mo < 4; mo++) {
            const float b0 = bs[mo * 16 + lrow];
            const float b1 = bs[mo * 16 + 8 + lrow];
            #pragma unroll
            for (int nt = 0; nt < 2; nt++) {
                c[mo][nt][0] = b0; c[mo][nt][1] = b0;
                c[mo][nt][2] = b1; c[mo][nt][3] = b1;
            }
        }
    }

    #pragma unroll
    for (int ks = 0; ks < 4; ks++) {
        // B frags (x, trans): x4 mats (k+lr, t)(k+lr, t+8)(k+8+lr, t)(k+8+lr, t+8)
        //   -> n-tile0 (t_loc+0..7):  {xh[0], xh[2]};  n-tile1 (t_loc+8..15): {xh[1], xh[3]}
        const int krow = ks * 16 + ((lm & 2) ? 8 : 0) + lr;
        const int tcol = t_loc + ((lm & 1) ? 8 : 0);
        const uint32_t ao = (uint32_t)krow * 272u + (uint32_t)tcol * 2u;
        uint32_t xh[4], xl[4];
        LDSM4T(xh, sb + XH_OFF + ao);
        LDSM4T(xl, sb + XL_OFF + ao);

        #pragma unroll
        for (int mo = 0; mo < 4; mo++) {
            // A frags (W, non-trans): x4 regs (o,k0)(o,k8)(o+8,k0)(o+8,k8)
            //   -> A order = {w[0], w[2], w[1], w[3]}
            const int orow = mo * 16 + ((lm & 2) ? 8 : 0) + lr;
            const int kcol = ks * 16 + ((lm & 1) ? 8 : 0);
            const uint32_t bo = (uint32_t)orow * 144u + (uint32_t)kcol * 2u;
            uint32_t wh[4], wl[4];
            LDSM4(wh, sb + WH_OFF + bo);
            LDSM4(wl, sb + WL_OFF + bo);
            // nt = 0
            MMA_R(c[mo][0], wh[0], wh[2], wh[1], wh[3], xh[0], xh[2]);
            MMA_R(c[mo][0], wh[0], wh[2], wh[1], wh[3], xl[0], xl[2]);
            MMA_R(c[mo][0], wl[0], wl[2], wl[1], wl[3], xh[0], xh[2]);
            // nt = 1
            MMA_R(c[mo][1], wh[0], wh[2], wh[1], wh[3], xh[1], xh[3]);
            MMA_R(c[mo][1], wh[0], wh[2], wh[1], wh[3], xl[1], xl[3]);
            MMA_R(c[mo][1], wl[0], wl[2], wl[1], wl[3], xh[1], xh[3]);
        }
    }

    // ---- Direct store: per (mo, nt): lane writes float2 at (o, t) and (o+8, t).
    //      Quad of lanes covers 8 consecutive t = 32B sector-aligned. ----
    #pragma unroll
    for (int mo = 0; mo < 4; mo++) {
        const int o0 = mo * 16 + lrow;
        #pragma unroll
        for (int nt = 0; nt < 2; nt++) {
            const int t = t_loc + nt * 8 + lcol2;
            float2 v0 = make_float2(c[mo][nt][0], c[mo][nt][1]);
            float2 v1 = make_float2(c[mo][nt][2], c[mo][nt][3]);
            *(float2*)(og + (size_t)o0 * T_DIM + t)       = v0;
            *(float2*)(og + (size_t)(o0 + 8) * T_DIM + t) = v1;
        }
    }
}

extern "C" void kernel_launch(void* const* d_in, const int* in_sizes, int n_in,
                              void* d_out, int out_size) {
    const float* x = (const float*)d_in[0];   // [E, 64, 256]
    const float* W = (const float*)d_in[1];   // [E, 64, 64]
    const float* b = (const float*)d_in[2];   // [E, 64]
    float*       o = (float*)d_out;           // [E, 64, 256]

    const int E = in_sizes[0] / (K_DIM * T_DIM);

    cudaFuncSetAttribute(pl_hmma_direct_kernel,
                         cudaFuncAttributeMaxDynamicSharedMemorySize, SMEM_BYTES);
    pl_hmma_direct_kernel<<<2 * E, 256, SMEM_BYTES>>>(x, W, b, o);
}

// round 12
// speedup vs baseline: 1.0682x; 1.0682x over previous
#include <cuda_runtime.h>
#include <cuda_bf16.h>
#include <cstdint>

// Per edge: out[o][t] = sum_k W[o][k] * x[k][t] + b[o],  O=K=64, T=256, E=10000
// mma.sync m16n8k16 bf16, 3-term split: D = xh*wh + xl*wh + xh*wl (rel ~2^-18).
// R12: one CTA per HALF-edge (128 t), 4 CTAs/SM. D[t][o] = x^T * W (m=t, n=o).
//   32x32 warp tiles (4 t-tiles x 2 o-tiles) cut LDSM traffic 20% vs 16x64.
//   Epilogue: per-warp XOR-swizzled 4KB patch, syncwarp only, coalesced STG.128.

#define T_DIM 256
#define K_DIM 64
#define O_DIM 64

// smem pitches (16B-chunk strides odd => conflict-free ldmatrix):
//   x: 136 bf16 = 272B = 17 chunks;  W: 72 bf16 = 144B = 9 chunks
#define WH_OFF   0u        // 64*144 = 9216
#define WL_OFF   9216u
#define BIAS_OFF 18432u    // 256B, pad to 18944
#define XH_OFF   18944u    // 64*272 = 17408 -> 36352
#define XL_OFF   36352u    // -> 53760
#define PAT_OFF  18944u    // epilogue patches overlay x: 8 warps * 4096B = 32768
#define SMEM_BYTES 53760

static __device__ __forceinline__ uint32_t s2u(const void* p) {
    uint32_t a;
    asm("{ .reg .u64 t; cvta.to.shared.u64 t, %1; cvt.u32.u64 %0, t; }" : "=r"(a) : "l"(p));
    return a;
}

// split (a,b) into packed bf16x2 hi and lo pairs (a -> low half, memory order)
static __device__ __forceinline__ void split2(float a, float b, uint32_t& hp, uint32_t& lp) {
    __nv_bfloat16 ha = __float2bfloat16(a), hb = __float2bfloat16(b);
    float ra = a - __bfloat162float(ha);
    float rb = b - __bfloat162float(hb);
    __nv_bfloat16 la = __float2bfloat16(ra), lb = __float2bfloat16(rb);
    hp = (uint32_t)__bfloat16_as_ushort(ha) | ((uint32_t)__bfloat16_as_ushort(hb) << 16);
    lp = (uint32_t)__bfloat16_as_ushort(la) | ((uint32_t)__bfloat16_as_ushort(lb) << 16);
}

#define LDSM4(r, addr) \
    asm volatile("ldmatrix.sync.aligned.m8n8.x4.shared.b16 {%0,%1,%2,%3}, [%4];" \
        : "=r"((r)[0]), "=r"((r)[1]), "=r"((r)[2]), "=r"((r)[3]) : "r"(addr))

#define LDSM4T(r, addr) \
    asm volatile("ldmatrix.sync.aligned.m8n8.x4.trans.shared.b16 {%0,%1,%2,%3}, [%4];" \
        : "=r"((r)[0]), "=r"((r)[1]), "=r"((r)[2]), "=r"((r)[3]) : "r"(addr))

#define MMA16816(c, a, b0, b1) \
    asm volatile("mma.sync.aligned.m16n8k16.row.col.f32.bf16.bf16.f32 " \
        "{%0,%1,%2,%3}, {%4,%5,%6,%7}, {%8,%9}, {%0,%1,%2,%3};" \
        : "+f"((c)[0]), "+f"((c)[1]), "+f"((c)[2]), "+f"((c)[3]) \
        : "r"((a)[0]), "r"((a)[1]), "r"((a)[2]), "r"((a)[3]), "r"(b0), "r"(b1))

__global__ void __launch_bounds__(256, 4)
pl_hmma_sq_kernel(const float* __restrict__ x, const float* __restrict__ W,
                  const float* __restrict__ b, float* __restrict__ out)
{
    extern __shared__ char base[];
    const uint32_t sb = s2u(base);

    const int tid = threadIdx.x, wid = tid >> 5, lane = tid & 31;
    const int e  = blockIdx.x >> 1;          // edge
    const int th = blockIdx.x & 1;           // t-half: siblings adjacent -> W L2-hits
    const float* xg = x + (size_t)e * (K_DIM * T_DIM) + th * 128;
    const float* wg = W + (size_t)e * (O_DIM * K_DIM);
    const float* bg = b + (size_t)e * O_DIM;
    float*       og = out + (size_t)e * (O_DIM * T_DIM) + th * 128;

    // ---- Stage W -> (wh, wl) bf16, pitch 144B; 8-float packets, STS.128 ----
    {
        #pragma unroll
        for (int i = 0; i < 2; i++) {
            const int f  = tid + (i << 8);         // 0..511 (8-float chunks)
            const int o  = f >> 3;
            const int k8 = f & 7;
            const float4 v0 = *(const float4*)(wg + (size_t)o * K_DIM + (k8 << 3));
            const float4 v1 = *(const float4*)(wg + (size_t)o * K_DIM + (k8 << 3) + 4);
            uint4 h, l;
            split2(v0.x, v0.y, h.x, l.x); split2(v0.z, v0.w, h.y, l.y);
            split2(v1.x, v1.y, h.z, l.z); split2(v1.z, v1.w, h.w, l.w);
            const uint32_t off = (uint32_t)o * 144u + (uint32_t)k8 * 16u;
            *(uint4*)(base + WH_OFF + off) = h;
            *(uint4*)(base + WL_OFF + off) = l;
        }
    }
    // ---- Stage x half -> (xh, xl) bf16, pitch 272B; STS.128 ----
    {
        #pragma unroll
        for (int i = 0; i < 4; i++) {
            const int f  = tid + (i << 8);         // 0..1023 (8-float chunks)
            const int k  = f >> 4;                 // 16 chunks per 128-t row
            const int c8 = f & 15;
            const float4 v0 = *(const float4*)(xg + (size_t)k * T_DIM + (c8 << 3));
            const float4 v1 = *(const float4*)(xg + (size_t)k * T_DIM + (c8 << 3) + 4);
            uint4 h, l;
            split2(v0.x, v0.y, h.x, l.x); split2(v0.z, v0.w, h.y, l.y);
            split2(v1.x, v1.y, h.z, l.z); split2(v1.z, v1.w, h.w, l.w);
            const uint32_t off = (uint32_t)k * 272u + (uint32_t)c8 * 16u;
            *(uint4*)(base + XH_OFF + off) = h;
            *(uint4*)(base + XL_OFF + off) = l;
        }
    }
    if (tid < 64) *(float*)(base + BIAS_OFF + tid * 4) = bg[tid];
    __syncthreads();

    // ---- Warp tile: t in [32*t_w, +32), o in [32*o_w, +32) ----
    const int t_w = wid & 3, o_w = wid >> 2;
    const int lrow  = lane >> 2;       // 0..7
    const int lcol2 = (lane & 3) << 1; // 0,2,4,6
    const int lm = lane >> 3, lr = lane & 7;

    // c[mi][nj][4]: t = 32t_w + 16mi + lrow (+8 for q>=2), o = 32o_w + 8nj + lcol2 (+q&1)
    float c[2][4][4];
    {
        const float* bs = (const float*)(base + BIAS_OFF) + (o_w << 5);
        #pragma unroll
        for (int nj = 0; nj < 4; nj++) {
            const float b0 = bs[nj * 8 + lcol2];
            const float b1 = bs[nj * 8 + lcol2 + 1];
            #pragma unroll
            for (int mi = 0; mi < 2; mi++) {
                c[mi][nj][0] = b0; c[mi][nj][1] = b1;
                c[mi][nj][2] = b0; c[mi][nj][3] = b1;
            }
        }
    }

    #pragma unroll
    for (int ks = 0; ks < 4; ks++) {
        // A frags (x, trans): per mi, mats (k r,t)(k r,t+8)(k+8,t)(k+8,t+8)
        uint32_t ah[2][4], al[2][4];
        const int krow = ks * 16 + ((lm & 2) ? 8 : 0) + lr;
        #pragma unroll
        for (int mi = 0; mi < 2; mi++) {
            const int tcol = (t_w << 5) + mi * 16 + ((lm & 1) ? 8 : 0);
            const uint32_t ao = (uint32_t)krow * 272u + (uint32_t)tcol * 2u;
            LDSM4T(ah[mi], sb + XH_OFF + ao);
            LDSM4T(al[mi], sb + XL_OFF + ao);
        }
        #pragma unroll
        for (int njp = 0; njp < 2; njp++) {
            const int orow = (o_w << 5) + njp * 16 + ((lm & 2) ? 8 : 0) + lr;
            const int kcol = ks * 16 + ((lm & 1) ? 8 : 0);
            const uint32_t bo = (uint32_t)orow * 144u + (uint32_t)kcol * 2u;
            uint32_t bh[4], bl[4];
            LDSM4(bh, sb + WH_OFF + bo);
            LDSM4(bl, sb + WL_OFF + bo);
            #pragma unroll
            for (int mi = 0; mi < 2; mi++) {
                MMA16816(c[mi][2 * njp],     ah[mi], bh[0], bh[1]);
                MMA16816(c[mi][2 * njp],     al[mi], bh[0], bh[1]);
                MMA16816(c[mi][2 * njp],     ah[mi], bl[0], bl[1]);
                MMA16816(c[mi][2 * njp + 1], ah[mi], bh[2], bh[3]);
                MMA16816(c[mi][2 * njp + 1], al[mi], bh[2], bh[3]);
                MMA16816(c[mi][2 * njp + 1], ah[mi], bl[2], bl[3]);
            }
        }
    }

    // ---- Epilogue: per-warp swizzled patch [o'][t'], 32x32 fl, bank = t'^((o'&7)<<2) ----
    __syncthreads();   // x smem region reused by patches
    {
        char* pat = base + PAT_OFF + (wid << 12);
        #pragma unroll
        for (int mi = 0; mi < 2; mi++)
            #pragma unroll
            for (int nj = 0; nj < 4; nj++)
                #pragma unroll
                for (int q = 0; q < 4; q++) {
                    const int tl = mi * 16 + lrow + ((q & 2) ? 8 : 0);
                    const int ol = nj * 8 + lcol2 + (q & 1);
                    const uint32_t word = (uint32_t)(ol << 5) + (uint32_t)(tl ^ ((ol & 7) << 2));
                    *(float*)(pat + (word << 2)) = c[mi][nj][q];
                }
        __syncwarp();

        const int c4w = (lane & 7) << 2;              // t' base of this lane's float4
        float* ogw = og + (size_t)(o_w << 5) * T_DIM + (t_w << 5) + c4w;
        #pragma unroll
        for (int i = 0; i < 8; i++) {
            const int ol = (i << 2) + (lane >> 3);
            const uint32_t word = (uint32_t)(ol << 5) + (uint32_t)(c4w ^ ((ol & 7) << 2));
            *(float4*)(ogw + (size_t)ol * T_DIM) = *(const float4*)(pat + (word << 2));
        }
    }
}

extern "C" void kernel_launch(void* const* d_in, const int* in_sizes, int n_in,
                              void* d_out, int out_size) {
    const float* x = (const float*)d_in[0];   // [E, 64, 256]
    const float* W = (const float*)d_in[1];   // [E, 64, 64]
    const float* b = (const float*)d_in[2];   // [E, 64]
    float*       o = (float*)d_out;           // [E, 64, 256]

    const int E = in_sizes[0] / (K_DIM * T_DIM);

    cudaFuncSetAttribute(pl_hmma_sq_kernel,
                         cudaFuncAttributeMaxDynamicSharedMemorySize, SMEM_BYTES);
    pl_hmma_sq_kernel<<<2 * E, 256, SMEM_BYTES>>>(x, W, b, o);
}

// round 13
// speedup vs baseline: 1.4215x; 1.3307x over previous
#include <cuda_runtime.h>
#include <cuda_fp16.h>
#include <cstdint>

// Per edge: out[o][t] = sum_k W[o][k] * x[k][t] + b[o],  O=K=64, T=256, E=10000
// mma.sync m16n8k16 f16, 2-term split of x only:
//   D = (xh + xl) * fp16(W);  x exact to ~2^-22, W rounded to fp16 (~2^-12 RMS)
//   => rel_err ~1e-4, well under 1e-3. 64 MMAs/warp (vs 96 for bf16 3-term).
// One CTA per HALF-edge (128 t), 4 CTAs/SM (reg-capped). D[t][o] = x^T * W.

#define T_DIM 256
#define K_DIM 64
#define O_DIM 64

// smem pitches (16B-chunk strides odd => conflict-free ldmatrix):
//   x: 136 f16 = 272B = 17 chunks;  W: 72 f16 = 144B = 9 chunks
#define WH_OFF   0u        // 64*144 = 9216
#define BIAS_OFF 9216u     // 256B, pad to 9472
#define XH_OFF   9472u     // 64*272 = 17408 -> 26880
#define XL_OFF   26880u    // -> 44288
#define OUT_OFF  9472u     // epilogue reuses x region: 64 rows * 528B = 33792 -> 43264
#define OPITCH_F 132       // floats; 132 mod 32 = 4 -> conflict-free scatter
#define SMEM_BYTES 44288

static __device__ __forceinline__ uint32_t s2u(const void* p) {
    uint32_t a;
    asm("{ .reg .u64 t; cvta.to.shared.u64 t, %1; cvt.u32.u64 %0, t; }" : "=r"(a) : "l"(p));
    return a;
}

// pack fp16(a), fp16(b) into one u32 (a -> low half)
static __device__ __forceinline__ uint32_t pack2h(float a, float b) {
    __half2 h = __floats2half2_rn(a, b);
    return *(uint32_t*)&h;
}
// split (a,b) into fp16 hi pair and fp16 lo (residual) pair
static __device__ __forceinline__ void split2h(float a, float b, uint32_t& hp, uint32_t& lp) {
    __half ha = __float2half_rn(a), hb = __float2half_rn(b);
    float ra = a - __half2float(ha);
    float rb = b - __half2float(hb);
    hp = (uint32_t)__half_as_ushort(ha) | ((uint32_t)__half_as_ushort(hb) << 16);
    lp = pack2h(ra, rb);
}

#define LDSM4(r, addr) \
    asm volatile("ldmatrix.sync.aligned.m8n8.x4.shared.b16 {%0,%1,%2,%3}, [%4];" \
        : "=r"((r)[0]), "=r"((r)[1]), "=r"((r)[2]), "=r"((r)[3]) : "r"(addr))

#define LDSM4T(r, addr) \
    asm volatile("ldmatrix.sync.aligned.m8n8.x4.trans.shared.b16 {%0,%1,%2,%3}, [%4];" \
        : "=r"((r)[0]), "=r"((r)[1]), "=r"((r)[2]), "=r"((r)[3]) : "r"(addr))

#define MMA16816H(c, a, b0, b1) \
    asm volatile("mma.sync.aligned.m16n8k16.row.col.f32.f16.f16.f32 " \
        "{%0,%1,%2,%3}, {%4,%5,%6,%7}, {%8,%9}, {%0,%1,%2,%3};" \
        : "+f"((c)[0]), "+f"((c)[1]), "+f"((c)[2]), "+f"((c)[3]) \
        : "r"((a)[0]), "r"((a)[1]), "r"((a)[2]), "r"((a)[3]), "r"(b0), "r"(b1))

__global__ void __launch_bounds__(256, 4)
pl_hmma_f16_kernel(const float* __restrict__ x, const float* __restrict__ W,
                   const float* __restrict__ b, float* __restrict__ out)
{
    extern __shared__ char base[];
    const uint32_t sb = s2u(base);

    const int tid = threadIdx.x, wid = tid >> 5, lane = tid & 31;
    const int e  = blockIdx.x >> 1;          // edge
    const int th = blockIdx.x & 1;           // t-half: siblings adjacent -> W L2-hits
    const float* xg = x + (size_t)e * (K_DIM * T_DIM) + th * 128;
    const float* wg = W + (size_t)e * (O_DIM * K_DIM);
    const float* bg = b + (size_t)e * O_DIM;
    float*       og = out + (size_t)e * (O_DIM * T_DIM) + th * 128;

    // ---- Stage W -> fp16 (hi only), pitch 144B ----
    {
        const float4* wg4 = (const float4*)wg;
        #pragma unroll
        for (int i = 0; i < 4; i++) {
            const int f  = tid + (i << 8);         // 0..1023 float4s
            const int o  = f >> 4;
            const int kc = f & 15;                 // float4 within row
            float4 v = wg4[f];
            uint2 h;
            h.x = pack2h(v.x, v.y);
            h.y = pack2h(v.z, v.w);
            *(uint2*)(base + WH_OFF + (uint32_t)o * 144u + (uint32_t)kc * 8u) = h;
        }
    }
    // ---- Stage x half -> (xh, xl) fp16, pitch 272B (128 t per row) ----
    {
        #pragma unroll
        for (int i = 0; i < 8; i++) {
            const int f  = tid + (i << 8);         // 0..2047 float4s
            const int k  = f >> 5;                 // 32 float4 per local row
            const int c4 = f & 31;
            float4 v = *(const float4*)(xg + (size_t)k * T_DIM + (c4 << 2));
            uint2 h, l;
            split2h(v.x, v.y, h.x, l.x);
            split2h(v.z, v.w, h.y, l.y);
            const uint32_t off = (uint32_t)k * 272u + (uint32_t)c4 * 8u;
            *(uint2*)(base + XH_OFF + off) = h;
            *(uint2*)(base + XL_OFF + off) = l;
        }
    }
    if (tid < 64) *(float*)(base + BIAS_OFF + tid * 4) = bg[tid];
    __syncthreads();

    // ---- Per-warp tile: t_loc in [16*wid, 16*wid+16), o in [0, 64) ----
    const int t_loc = wid << 4;
    const int lrow = lane >> 2;        // 0..7
    const int lcol2 = (lane & 3) << 1; // 0,2,4,6
    const int lm = lane >> 3, lr = lane & 7;

    float c[8][4];
    {
        const float* bs = (const float*)(base + BIAS_OFF);
        #pragma unroll
        for (int nj = 0; nj < 8; nj++) {
            const float b0 = bs[nj * 8 + lcol2];
            const float b1 = bs[nj * 8 + lcol2 + 1];
            c[nj][0] = b0; c[nj][1] = b1; c[nj][2] = b0; c[nj][3] = b1;
        }
    }

    #pragma unroll
    for (int ks = 0; ks < 4; ks++) {
        // A frags (x, trans): mats (k r,t)(k r,t+8)(k+8,t)(k+8,t+8)
        const int krow = ks * 16 + ((lm & 2) ? 8 : 0) + lr;
        const int tcol = t_loc + ((lm & 1) ? 8 : 0);
        const uint32_t ao = (uint32_t)krow * 272u + (uint32_t)tcol * 2u;
        uint32_t ah[4], al[4];
        LDSM4T(ah, sb + XH_OFF + ao);
        LDSM4T(al, sb + XL_OFF + ao);

        #pragma unroll
        for (int njp = 0; njp < 4; njp++) {
            const int orow = njp * 16 + ((lm & 2) ? 8 : 0) + lr;
            const int kcol = ks * 16 + ((lm & 1) ? 8 : 0);
            const uint32_t bo = (uint32_t)orow * 144u + (uint32_t)kcol * 2u;
            uint32_t bh[4];
            LDSM4(bh, sb + WH_OFF + bo);
            MMA16816H(c[2 * njp],     ah, bh[0], bh[1]);
            MMA16816H(c[2 * njp],     al, bh[0], bh[1]);
            MMA16816H(c[2 * njp + 1], ah, bh[2], bh[3]);
            MMA16816H(c[2 * njp + 1], al, bh[2], bh[3]);
        }
    }

    // ---- Epilogue: scatter c -> smem [o][t_loc] (pitch 132 fl), then coalesced stores ----
    __syncthreads();   // x smem region reused
    float* outp = (float*)(base + OUT_OFF);
    #pragma unroll
    for (int nj = 0; nj < 8; nj++)
        #pragma unroll
        for (int q = 0; q < 4; q++) {
            const int t = t_loc + lrow + ((q & 2) ? 8 : 0);
            const int o = nj * 8 + lcol2 + (q & 1);
            outp[o * OPITCH_F + t] = c[nj][q];
        }
    __syncthreads();

    #pragma unroll
    for (int i = 0; i < 8; i++) {
        const int idx = tid + (i << 8);       // 0..2047 float4s
        const int row = idx >> 5;             // o
        const int c4  = idx & 31;             // local t float4
        *(float4*)(og + (size_t)row * T_DIM + (c4 << 2)) =
            *(const float4*)(base + OUT_OFF + (uint32_t)row * 528u + (uint32_t)c4 * 16u);
    }
}

extern "C" void kernel_launch(void* const* d_in, const int* in_sizes, int n_in,
                              void* d_out, int out_size) {
    const float* x = (const float*)d_in[0];   // [E, 64, 256]
    const float* W = (const float*)d_in[1];   // [E, 64, 64]
    const float* b = (const float*)d_in[2];   // [E, 64]
    float*       o = (float*)d_out;           // [E, 64, 256]

    const int E = in_sizes[0] / (K_DIM * T_DIM);

    cudaFuncSetAttribute(pl_hmma_f16_kernel,
                         cudaFuncAttributeMaxDynamicSharedMemorySize, SMEM_BYTES);
    pl_hmma_f16_kernel<<<2 * E, 256, SMEM_BYTES>>>(x, W, b, o);
}

// round 15
// speedup vs baseline: 1.4790x; 1.0405x over previous
#include <cuda_runtime.h>
#include <cuda_fp16.h>
#include <cstdint>

// Per edge: out[o][t] = sum_k W[o][k] * x[k][t] + b[o],  O=K=64, T=256, E=10000
// mma.sync m16n8k16 f16, both operands fp16-rounded, fp32 accumulate:
//   error ~ sqrt(2) * (W-only fp16 error 2.05e-4) ~ 2.9e-4 << 1e-3.
// One CTA per HALF-edge (128 t), 4 CTAs/SM (reg-capped). D[t][o] = x^T * W.
// 32 MMAs/warp; single-precision staging; epilogue smem transpose for
// coalesced STG.128.

#define T_DIM 256
#define K_DIM 64
#define O_DIM 64

// smem pitches (16B-chunk strides odd => conflict-free ldmatrix):
//   x: 136 f16 = 272B = 17 chunks;  W: 72 f16 = 144B = 9 chunks
#define WH_OFF   0u        // 64*144 = 9216
#define BIAS_OFF 9216u     // 256B, pad to 9472
#define XH_OFF   9472u     // 64*272 = 17408 -> 26880
#define OUT_OFF  0u        // epilogue overlays EVERYTHING (W/bias/x dead): 64*528 = 33792
#define OPITCH_F 132       // floats; 132 mod 32 = 4 -> conflict-free scatter
#define SMEM_BYTES 33792

static __device__ __forceinline__ uint32_t s2u(const void* p) {
    uint32_t a;
    asm("{ .reg .u64 t; cvta.to.shared.u64 t, %1; cvt.u32.u64 %0, t; }" : "=r"(a) : "l"(p));
    return a;
}

// pack fp16(a), fp16(b) into one u32 (a -> low half)
static __device__ __forceinline__ uint32_t pack2h(float a, float b) {
    __half2 h = __floats2half2_rn(a, b);
    return *(uint32_t*)&h;
}

#define LDSM4(r, addr) \
    asm volatile("ldmatrix.sync.aligned.m8n8.x4.shared.b16 {%0,%1,%2,%3}, [%4];" \
        : "=r"((r)[0]), "=r"((r)[1]), "=r"((r)[2]), "=r"((r)[3]) : "r"(addr))

#define LDSM4T(r, addr) \
    asm volatile("ldmatrix.sync.aligned.m8n8.x4.trans.shared.b16 {%0,%1,%2,%3}, [%4];" \
        : "=r"((r)[0]), "=r"((r)[1]), "=r"((r)[2]), "=r"((r)[3]) : "r"(addr))

#define MMA16816H(c, a, b0, b1) \
    asm volatile("mma.sync.aligned.m16n8k16.row.col.f32.f16.f16.f32 " \
        "{%0,%1,%2,%3}, {%4,%5,%6,%7}, {%8,%9}, {%0,%1,%2,%3};" \
        : "+f"((c)[0]), "+f"((c)[1]), "+f"((c)[2]), "+f"((c)[3]) \
        : "r"((a)[0]), "r"((a)[1]), "r"((a)[2]), "r"((a)[3]), "r"(b0), "r"(b1))

__global__ void __launch_bounds__(256, 4)
pl_hmma_pf16_kernel(const float* __restrict__ x, const float* __restrict__ W,
                    const float* __restrict__ b, float* __restrict__ out)
{
    extern __shared__ char base[];
    const uint32_t sb = s2u(base);

    const int tid = threadIdx.x, wid = tid >> 5, lane = tid & 31;
    const int e  = blockIdx.x >> 1;          // edge
    const int th = blockIdx.x & 1;           // t-half: siblings adjacent -> W L2-hits
    const float* xg = x + (size_t)e * (K_DIM * T_DIM) + th * 128;
    const float* wg = W + (size_t)e * (O_DIM * K_DIM);
    const float* bg = b + (size_t)e * O_DIM;
    float*       og = out + (size_t)e * (O_DIM * T_DIM) + th * 128;

    // ---- Stage W -> fp16, pitch 144B ----
    {
        const float4* wg4 = (const float4*)wg;
        #pragma unroll
        for (int i = 0; i < 4; i++) {
            const int f  = tid + (i << 8);         // 0..1023 float4s
            const int o  = f >> 4;
            const int kc = f & 15;                 // float4 within row
            float4 v = wg4[f];
            uint2 h;
            h.x = pack2h(v.x, v.y);
            h.y = pack2h(v.z, v.w);
            *(uint2*)(base + WH_OFF + (uint32_t)o * 144u + (uint32_t)kc * 8u) = h;
        }
    }
    // ---- Stage x half -> fp16, pitch 272B (128 t per row) ----
    {
        #pragma unroll
        for (int i = 0; i < 8; i++) {
            const int f  = tid + (i << 8);         // 0..2047 float4s
            const int k  = f >> 5;                 // 32 float4 per local row
            const int c4 = f & 31;
            float4 v = *(const float4*)(xg + (size_t)k * T_DIM + (c4 << 2));
            uint2 h;
            h.x = pack2h(v.x, v.y);
            h.y = pack2h(v.z, v.w);
            *(uint2*)(base + XH_OFF + (uint32_t)k * 272u + (uint32_t)c4 * 8u) = h;
        }
    }
    if (tid < 64) *(float*)(base + BIAS_OFF + tid * 4) = bg[tid];
    __syncthreads();

    // ---- Per-warp tile: t_loc in [16*wid, 16*wid+16), o in [0, 64) ----
    const int t_loc = wid << 4;
    const int lrow = lane >> 2;        // 0..7
    const int lcol2 = (lane & 3) << 1; // 0,2,4,6
    const int lm = lane >> 3, lr = lane & 7;

    float c[8][4];
    {
        const float* bs = (const float*)(base + BIAS_OFF);
        #pragma unroll
        for (int nj = 0; nj < 8; nj++) {
            const float b0 = bs[nj * 8 + lcol2];
            const float b1 = bs[nj * 8 + lcol2 + 1];
            c[nj][0] = b0; c[nj][1] = b1; c[nj][2] = b0; c[nj][3] = b1;
        }
    }

    #pragma unroll
    for (int ks = 0; ks < 4; ks++) {
        // A frags (x, trans): mats (k r,t)(k r,t+8)(k+8,t)(k+8,t+8)
        const int krow = ks * 16 + ((lm & 2) ? 8 : 0) + lr;
        const int tcol = t_loc + ((lm & 1) ? 8 : 0);
        const uint32_t ao = (uint32_t)krow * 272u + (uint32_t)tcol * 2u;
        uint32_t ah[4];
        LDSM4T(ah, sb + XH_OFF + ao);

        #pragma unroll
        for (int njp = 0; njp < 4; njp++) {
            const int orow = njp * 16 + ((lm & 2) ? 8 : 0) + lr;
            const int kcol = ks * 16 + ((lm & 1) ? 8 : 0);
            const uint32_t bo = (uint32_t)orow * 144u + (uint32_t)kcol * 2u;
            uint32_t bh[4];
            LDSM4(bh, sb + WH_OFF + bo);
            MMA16816H(c[2 * njp],     ah, bh[0], bh[1]);
            MMA16816H(c[2 * njp + 1], ah, bh[2], bh[3]);
        }
    }

    // ---- Epilogue: scatter c -> smem [o][t_loc] (pitch 132 fl), then coalesced stores ----
    __syncthreads();   // whole smem reused (W/bias/x all dead)
    float* outp = (float*)(base + OUT_OFF);
    #pragma unroll
    for (int nj = 0; nj < 8; nj++)
        #pragma unroll
        for (int q = 0; q < 4; q++) {
            const int t = t_loc + lrow + ((q & 2) ? 8 : 0);
            const int o = nj * 8 + lcol2 + (q & 1);
            outp[o * OPITCH_F + t] = c[nj][q];
        }
    __syncthreads();

    #pragma unroll
    for (int i = 0; i < 8; i++) {
        const int idx = tid + (i << 8);       // 0..2047 float4s
        const int row = idx >> 5;             // o
        const int c4  = idx & 31;             // local t float4
        *(float4*)(og + (size_t)row * T_DIM + (c4 << 2)) =
            *(const float4*)(base + OUT_OFF + (uint32_t)row * 528u + (uint32_t)c4 * 16u);
    }
}

extern "C" void kernel_launch(void* const* d_in, const int* in_sizes, int n_in,
                              void* d_out, int out_size) {
    const float* x = (const float*)d_in[0];   // [E, 64, 256]
    const float* W = (const float*)d_in[1];   // [E, 64, 64]
    const float* b = (const float*)d_in[2];   // [E, 64]
    float*       o = (float*)d_out;           // [E, 64, 256]

    const int E = in_sizes[0] / (K_DIM * T_DIM);

    cudaFuncSetAttribute(pl_hmma_pf16_kernel,
                         cudaFuncAttributeMaxDynamicSharedMemorySize, SMEM_BYTES);
    pl_hmma_pf16_kernel<<<2 * E, 256, SMEM_BYTES>>>(x, W, b, o);
}